// round 3
// baseline (speedup 1.0000x reference)
#include <cuda_runtime.h>

// TT embedding lookup, GB300 sm_103a.
// Shapes: lS_i [2,1024] (int32 OR int64 -- runtime-probed);
//         core0 [2,216,256] f32; core1 [2,216,65536] f32;
//         core2 [2,216,256] f32; out [2,1024,16] f32.
// Math per sample: out[q0,q1,q2] = sum_{r0,r1} A[q0,r0] * Bm[r0,q1,r1] * C[r1,q2]
//   A  = core0 row, flat q0*128 + r0
//   Bm = core1 row, flat r0*512 + q1*128 + r1
//   C  = core2 row, flat r1*2 + q2

#define NTAB   2
#define BATCH  1024
#define PDIM   216
#define P12    46656    // 216*216
#define R0DIM  128

__device__ int g_idx_is64;   // 1 if lS_i is int64, 0 if int32

// Probe: int64 data with values in [0, 2^32) has zero high words at every
// odd int32 position. 32 consecutive zero odd-words from random int32
// indices in [0, 1e7) is probability ~0.
__global__ void probe_dtype_kernel(const int* __restrict__ raw)
{
    int is64 = 1;
#pragma unroll
    for (int k = 0; k < 32; k++)
        if (raw[2 * k + 1] != 0) is64 = 0;
    g_idx_is64 = is64;
}

__global__ __launch_bounds__(128, 8)
void tt_lookup_kernel(const void* __restrict__ lS_i_raw,
                      const float* __restrict__ core0,
                      const float* __restrict__ core1,
                      const float* __restrict__ core2,
                      float* __restrict__ out)
{
    const int b    = blockIdx.x;     // batch index
    const int t    = blockIdx.y;     // table index
    const int tid  = threadIdx.x;
    const int warp = tid >> 5;
    const int lane = tid & 31;

    // dtype-robust index fetch
    const int pos = t * BATCH + b;
    long long idx;
    if (g_idx_is64)
        idx = ((const long long*)lS_i_raw)[pos];
    else
        idx = (long long)((const int*)lS_i_raw)[pos];

    // mixed-radix decomposition, clamped defensively (valid data is in range)
    int i0 = (int)(idx / P12);
    int i1 = (int)((idx / PDIM) % PDIM);
    int i2 = (int)(idx % PDIM);
    i0 = min(max(i0, 0), PDIM - 1);
    i1 = min(max(i1, 0), PDIM - 1);
    i2 = min(max(i2, 0), PDIM - 1);

    const float*  Arow = core0 + ((size_t)t * PDIM + i0) * 256;
    const float4* Brow = (const float4*)(core1 + ((size_t)t * PDIM + i1) * 65536);
    const float4* Crow = (const float4*)(core2 + ((size_t)t * PDIM + i2) * 256);

    __shared__ float sA[256];        // A row: [q0*128 + r0]
    __shared__ float sOut[4][16];    // per-warp partial outputs

    // Load A cooperatively (coalesced)
    sA[tid]       = Arow[tid];
    sA[128 + tid] = Arow[128 + tid];
    __syncthreads();

    // Per-lane C chunk: r1 in [lane*4, lane*4+4). Row layout r1*2+q2, so
    // floats [lane*8, lane*8+8) = 2 float4 (coalesced across the warp).
    const float4 cv0 = Crow[lane * 2 + 0];
    const float4 cv1 = Crow[lane * 2 + 1];
    const float c00 = cv0.x, c01 = cv0.y;   // r1 offset 0
    const float c10 = cv0.z, c11 = cv0.w;   // r1 offset 1
    const float c20 = cv1.x, c21 = cv1.y;   // r1 offset 2
    const float c30 = cv1.z, c31 = cv1.w;   // r1 offset 3

    float acc[16];
#pragma unroll
    for (int i = 0; i < 16; i++) acc[i] = 0.f;

    // Each warp owns r0 = warp, warp+4, ... Whole warp reads one Bm row
    // cooperatively: per q1 the 32 lanes' float4s cover a contiguous 512B
    // span -> 4 cache lines per LDG.128 (fully coalesced).
    for (int r0 = warp; r0 < R0DIM; r0 += 4) {
        const float4* bp = Brow + r0 * 128;   // row base in float4 units
        const float a0 = sA[r0];              // LDS broadcast (same addr/warp)
        const float a1 = sA[128 + r0];
#pragma unroll
        for (int q1 = 0; q1 < 4; q1++) {
            const float4 bv = bp[q1 * 32 + lane];
            // t[q1][q2] partial over this lane's 4 r1 values
            const float t0 = bv.x * c00 + bv.y * c10 + bv.z * c20 + bv.w * c30;
            const float t1 = bv.x * c01 + bv.y * c11 + bv.z * c21 + bv.w * c31;
            acc[0 + q1 * 2 + 0] += a0 * t0;   // q0 = 0
            acc[0 + q1 * 2 + 1] += a0 * t1;
            acc[8 + q1 * 2 + 0] += a1 * t0;   // q0 = 1
            acc[8 + q1 * 2 + 1] += a1 * t1;
        }
    }

    // Intra-warp butterfly reduction: after this every lane holds all 16 sums.
#pragma unroll
    for (int off = 16; off; off >>= 1) {
#pragma unroll
        for (int i = 0; i < 16; i++)
            acc[i] += __shfl_xor_sync(0xffffffffu, acc[i], off);
    }

    if (lane < 16) sOut[warp][lane] = acc[lane];
    __syncthreads();

    if (tid < 16) {
        const float v = sOut[0][tid] + sOut[1][tid] + sOut[2][tid] + sOut[3][tid];
        out[((size_t)t * BATCH + b) * 16 + tid] = v;
    }
}

extern "C" void kernel_launch(void* const* d_in, const int* in_sizes, int n_in,
                              void* d_out, int out_size)
{
    const void*  lS_i  = d_in[0];
    const float* core0 = (const float*)d_in[1];
    const float* core1 = (const float*)d_in[2];
    const float* core2 = (const float*)d_in[3];
    float*       out   = (float*)d_out;

    probe_dtype_kernel<<<1, 1>>>((const int*)lS_i);

    dim3 grid(BATCH, NTAB);
    tt_lookup_kernel<<<grid, 128>>>(lS_i, core0, core1, core2, out);
}